// round 4
// baseline (speedup 1.0000x reference)
#include <cuda_runtime.h>
#include <math.h>
#include <stdint.h>

// Problem constants
#define BB 4
#define LL 2048
#define DM 1024
#define NH 16
#define DH 64
#define MM (BB*LL)          // 8192 rows
#define ELEMS (MM*DM)       // 8388608 floats per tensor

__device__ float g_scratch[5 * 8388608];

#define CVT_TF32(u, f) asm("cvt.rna.tf32.f32 %0, %1;" : "=r"(u) : "f"(f))
__device__ __forceinline__ uint32_t fau(float f) { return __float_as_uint(f); }
__device__ __forceinline__ float uaf(uint32_t u) { return __uint_as_float(u); }

__device__ __forceinline__ void mma_tf32(float c[4],
                                         const uint32_t a[4],
                                         const uint32_t b[2]) {
    asm volatile(
        "mma.sync.aligned.m16n8k8.row.col.f32.tf32.tf32.f32 "
        "{%0,%1,%2,%3}, {%4,%5,%6,%7}, {%8,%9}, {%0,%1,%2,%3};\n"
        : "+f"(c[0]), "+f"(c[1]), "+f"(c[2]), "+f"(c[3])
        : "r"(a[0]), "r"(a[1]), "r"(a[2]), "r"(a[3]),
          "r"(b[0]), "r"(b[1]));
}

// ---------------------------------------------------------------------------
// LayerNorm
// ---------------------------------------------------------------------------
__global__ __launch_bounds__(256) void ln_kernel(const float* __restrict__ x,
                                                 const float* __restrict__ gamma,
                                                 const float* __restrict__ beta,
                                                 float* __restrict__ xn) {
    const int row = blockIdx.x;
    const int t = threadIdx.x;
    const float4 v = ((const float4*)(x + (size_t)row * DM))[t];
    __shared__ float red[8];

    float s = v.x + v.y + v.z + v.w;
#pragma unroll
    for (int o = 16; o > 0; o >>= 1) s += __shfl_xor_sync(0xffffffffu, s, o);
    if ((t & 31) == 0) red[t >> 5] = s;
    __syncthreads();
    float mean = (red[0]+red[1]+red[2]+red[3]+red[4]+red[5]+red[6]+red[7]) * (1.0f/DM);

    float dx = v.x-mean, dy = v.y-mean, dz = v.z-mean, dw = v.w-mean;
    float q = dx*dx + dy*dy + dz*dz + dw*dw;
#pragma unroll
    for (int o = 16; o > 0; o >>= 1) q += __shfl_xor_sync(0xffffffffu, q, o);
    __syncthreads();
    if ((t & 31) == 0) red[t >> 5] = q;
    __syncthreads();
    float var = (red[0]+red[1]+red[2]+red[3]+red[4]+red[5]+red[6]+red[7]) * (1.0f/DM);
    float rs = rsqrtf(var + 1e-5f);

    const float4 g4 = ((const float4*)gamma)[t];
    const float4 b4 = ((const float4*)beta)[t];
    float4 o4;
    o4.x = dx*rs*g4.x + b4.x;
    o4.y = dy*rs*g4.y + b4.y;
    o4.z = dz*rs*g4.z + b4.z;
    o4.w = dw*rs*g4.w + b4.w;
    ((float4*)(xn + (size_t)row * DM))[t] = o4;
}

// ---------------------------------------------------------------------------
// TF32 tensor-core GEMM (unchanged from round 2)
// ---------------------------------------------------------------------------
template <bool RESID>
__global__ __launch_bounds__(256) void tgemm_kernel(const float* __restrict__ A,
                                                    const float* __restrict__ W,
                                                    const float* __restrict__ bias,
                                                    const float* __restrict__ resid,
                                                    float* __restrict__ C) {
    constexpr int K = 1024, N = 1024;
    __shared__ float As[16][136];
    __shared__ float Bs[16][136];

    const int tid   = threadIdx.x;
    const int lane  = tid & 31;
    const int warp  = tid >> 5;
    const int warpM = warp >> 2;
    const int warpN = warp & 3;
    const int brow  = blockIdx.y;
    const int bcol  = blockIdx.x;

    const int aRow = tid >> 1;
    const int aCol = (tid & 1) << 3;
    const int bRow = tid >> 4;
    const int bCol = ((2 * tid) & 31) << 2;

    const float* Ab = A + (size_t)brow * 128 * K;
    const float* Wb = W + (size_t)bcol * 128;

    float acc[16][4];
#pragma unroll
    for (int i = 0; i < 16; i++)
#pragma unroll
        for (int j = 0; j < 4; j++) acc[i][j] = 0.f;

    uint32_t ar[8], br[8];

    auto load_regs = [&](int k0) {
        float4 a0 = *(const float4*)(Ab + (size_t)aRow * K + k0 + aCol);
        float4 a1 = *(const float4*)(Ab + (size_t)aRow * K + k0 + aCol + 4);
        CVT_TF32(ar[0], a0.x); CVT_TF32(ar[1], a0.y);
        CVT_TF32(ar[2], a0.z); CVT_TF32(ar[3], a0.w);
        CVT_TF32(ar[4], a1.x); CVT_TF32(ar[5], a1.y);
        CVT_TF32(ar[6], a1.z); CVT_TF32(ar[7], a1.w);
        float4 b0 = *(const float4*)(Wb + (size_t)(k0 + bRow) * N + bCol);
        float4 b1 = *(const float4*)(Wb + (size_t)(k0 + bRow) * N + bCol + 4);
        CVT_TF32(br[0], b0.x); CVT_TF32(br[1], b0.y);
        CVT_TF32(br[2], b0.z); CVT_TF32(br[3], b0.w);
        CVT_TF32(br[4], b1.x); CVT_TF32(br[5], b1.y);
        CVT_TF32(br[6], b1.z); CVT_TF32(br[7], b1.w);
    };

    auto store_smem = [&]() {
#pragma unroll
        for (int q = 0; q < 8; q++)
            As[aCol + q][aRow] = uaf(ar[q]);
        uint4 u0 = make_uint4(br[0], br[1], br[2], br[3]);
        uint4 u1 = make_uint4(br[4], br[5], br[6], br[7]);
        *(uint4*)(&Bs[bRow][bCol])     = u0;
        *(uint4*)(&Bs[bRow][bCol + 4]) = u1;
    };

    auto compute = [&]() {
#pragma unroll
        for (int ks = 0; ks < 2; ks++) {
            const int kb = (ks << 3) + (lane & 3);
            uint32_t af[4][4];
            uint32_t bf[4][2];
#pragma unroll
            for (int i = 0; i < 4; i++) {
                const int m = warpM * 64 + i * 16 + (lane >> 2);
                af[i][0] = fau(As[kb][m]);
                af[i][1] = fau(As[kb][m + 8]);
                af[i][2] = fau(As[kb + 4][m]);
                af[i][3] = fau(As[kb + 4][m + 8]);
            }
#pragma unroll
            for (int j = 0; j < 4; j++) {
                const int n = warpN * 32 + j * 8 + (lane >> 2);
                bf[j][0] = fau(Bs[kb][n]);
                bf[j][1] = fau(Bs[kb + 4][n]);
            }
#pragma unroll
            for (int i = 0; i < 4; i++)
#pragma unroll
                for (int j = 0; j < 4; j++)
                    mma_tf32(acc[i * 4 + j], af[i], bf[j]);
        }
    };

    load_regs(0);
    store_smem();
    __syncthreads();
    for (int k0 = 16; k0 < K; k0 += 16) {
        load_regs(k0);
        compute();
        __syncthreads();
        store_smem();
        __syncthreads();
    }
    compute();

#pragma unroll
    for (int i = 0; i < 4; i++) {
        const int r0 = brow * 128 + warpM * 64 + i * 16 + (lane >> 2);
#pragma unroll
        for (int j = 0; j < 4; j++) {
            const int cc = bcol * 128 + warpN * 32 + j * 8 + ((lane & 3) << 1);
            const float bx = bias[cc], by = bias[cc + 1];
            float v0x = acc[i * 4 + j][0] + bx;
            float v0y = acc[i * 4 + j][1] + by;
            float v1x = acc[i * 4 + j][2] + bx;
            float v1y = acc[i * 4 + j][3] + by;
            if (RESID) {
                const float2 r0v = *(const float2*)(resid + (size_t)r0 * N + cc);
                const float2 r1v = *(const float2*)(resid + (size_t)(r0 + 8) * N + cc);
                v0x += r0v.x; v0y += r0v.y;
                v1x += r1v.x; v1y += r1v.y;
            }
            *(float2*)(C + (size_t)r0 * N + cc)       = make_float2(v0x, v0y);
            *(float2*)(C + (size_t)(r0 + 8) * N + cc) = make_float2(v1x, v1y);
        }
    }
}

// ---------------------------------------------------------------------------
// RoPE
// ---------------------------------------------------------------------------
__global__ __launch_bounds__(256) void rope_kernel(float* __restrict__ q,
                                                   float* __restrict__ k) {
    const int idx = blockIdx.x * 256 + threadIdx.x;
    const int p = idx & 31;
    const int l = (idx >> 9) & 2047;

    const float e = (float)p * (-2.0f / 64.0f);
    const float inv = exp2f(e * 13.2877123795494f);
    const float ang = (float)l * inv;
    float s, c;
    sincosf(ang, &s, &c);

    const size_t off = (size_t)idx * 2;
    const float q1 = q[off], q2 = q[off + 1];
    q[off]     = q1 * c - q2 * s;
    q[off + 1] = q1 * s + q2 * c;
    const float k1 = k[off], k2 = k[off + 1];
    k[off]     = k1 * c - k2 * s;
    k[off + 1] = k1 * s + k2 * c;
}

// ---------------------------------------------------------------------------
// Tensor-core flash attention (causal, TF32 mma)
// Block: 4 warps. Q tile 128 rows (32/warp = 2 x m16), KV tile 64, d=64.
// ---------------------------------------------------------------------------
#define AST 68   // smem row stride (floats)

__global__ __launch_bounds__(128) void attn_tc_kernel(const float* __restrict__ qg,
                                                      const float* __restrict__ kg,
                                                      const float* __restrict__ vg,
                                                      float* __restrict__ og) {
    extern __shared__ float sm[];
    float* Qs = sm;                    // [128][AST]
    float* Ks = sm + 128 * AST;        // [64][AST]
    float* Vs = Ks + 64 * AST;         // [64][AST]

    const int bh = blockIdx.y;
    const int b = bh >> 4, h = bh & 15;
    const int qt = (int)gridDim.x - 1 - (int)blockIdx.x;   // heavy tiles first
    const int qbase = qt * 128;
    const int tid  = threadIdx.x;
    const int lane = tid & 31;
    const int warp = tid >> 5;
    const int g  = lane >> 2;   // 0..7
    const int l4 = lane & 3;    // 0..3

    // ---- load Q tile: 128 rows x 64 d, scale 1/8, cvt tf32 ----
    const float4* qgp = (const float4*)qg;
    for (int i = tid; i < 128 * 16; i += 128) {
        const int row = i >> 4, q4 = i & 15;
        float4 v = qgp[(size_t)(b * LL + qbase + row) * 256 + h * 16 + q4];
        uint32_t u0, u1, u2, u3;
        CVT_TF32(u0, v.x * 0.125f);
        CVT_TF32(u1, v.y * 0.125f);
        CVT_TF32(u2, v.z * 0.125f);
        CVT_TF32(u3, v.w * 0.125f);
        float* dst = Qs + row * AST + q4 * 4;
        dst[0] = uaf(u0); dst[1] = uaf(u1); dst[2] = uaf(u2); dst[3] = uaf(u3);
    }

    float s[2][8][4];
    float o[2][8][4];
#pragma unroll
    for (int mt = 0; mt < 2; mt++)
#pragma unroll
        for (int n = 0; n < 8; n++)
#pragma unroll
            for (int i = 0; i < 4; i++) o[mt][n][i] = 0.f;
    float mrow[4] = {-1e30f, -1e30f, -1e30f, -1e30f};
    float lrow[4] = {0.f, 0.f, 0.f, 0.f};

    const int ntiles = 2 * qt + 2;
    for (int t64 = 0; t64 < ntiles; t64++) {
        const int j0 = t64 * 64;
        __syncthreads();
        // ---- load K,V tile (64 rows x 64 d), cvt tf32 ----
        for (int i = tid; i < 64 * 16; i += 128) {
            const int row = i >> 4, q4 = i & 15;
            const size_t gi = (size_t)(b * LL + j0 + row) * 256 + h * 16 + q4;
            float4 kv = ((const float4*)kg)[gi];
            float4 vv = ((const float4*)vg)[gi];
            uint32_t u0, u1, u2, u3;
            CVT_TF32(u0, kv.x); CVT_TF32(u1, kv.y);
            CVT_TF32(u2, kv.z); CVT_TF32(u3, kv.w);
            float* kd = Ks + row * AST + q4 * 4;
            kd[0] = uaf(u0); kd[1] = uaf(u1); kd[2] = uaf(u2); kd[3] = uaf(u3);
            CVT_TF32(u0, vv.x); CVT_TF32(u1, vv.y);
            CVT_TF32(u2, vv.z); CVT_TF32(u3, vv.w);
            float* vd = Vs + row * AST + q4 * 4;
            vd[0] = uaf(u0); vd[1] = uaf(u1); vd[2] = uaf(u2); vd[3] = uaf(u3);
        }
        __syncthreads();

        // ---- S = Q @ K^T ----
#pragma unroll
        for (int mt = 0; mt < 2; mt++)
#pragma unroll
            for (int n = 0; n < 8; n++)
#pragma unroll
                for (int i = 0; i < 4; i++) s[mt][n][i] = 0.f;

#pragma unroll
        for (int kk = 0; kk < 8; kk++) {
            uint32_t qa[2][4];
#pragma unroll
            for (int mt = 0; mt < 2; mt++) {
                const float* qp = Qs + (warp * 32 + mt * 16 + g) * AST + kk * 8 + l4;
                qa[mt][0] = fau(qp[0]);
                qa[mt][2] = fau(qp[4]);
                qa[mt][1] = fau(qp[8 * AST]);
                qa[mt][3] = fau(qp[8 * AST + 4]);
            }
#pragma unroll
            for (int n = 0; n < 8; n++) {
                uint32_t kb[2];
                const float* kp = Ks + (n * 8 + g) * AST + kk * 8 + l4;
                kb[0] = fau(kp[0]);
                kb[1] = fau(kp[4]);
                mma_tf32(s[0][n], qa[0], kb);
                mma_tf32(s[1][n], qa[1], kb);
            }
        }

        // ---- causal mask (only last two tiles can clip) ----
        if (t64 >= 2 * qt) {
#pragma unroll
            for (int mt = 0; mt < 2; mt++) {
                const int rg = qbase + warp * 32 + mt * 16 + g;
#pragma unroll
                for (int n = 0; n < 8; n++) {
                    const int c0 = j0 + n * 8 + 2 * l4;
                    if (c0     > rg)     s[mt][n][0] = -1e30f;
                    if (c0 + 1 > rg)     s[mt][n][1] = -1e30f;
                    if (c0     > rg + 8) s[mt][n][2] = -1e30f;
                    if (c0 + 1 > rg + 8) s[mt][n][3] = -1e30f;
                }
            }
        }

        // ---- online softmax (rows r, r+8 per m-tile) ----
#pragma unroll
        for (int mt = 0; mt < 2; mt++) {
            float r0 = -1e30f, r1 = -1e30f;
#pragma unroll
            for (int n = 0; n < 8; n++) {
                r0 = fmaxf(r0, fmaxf(s[mt][n][0], s[mt][n][1]));
                r1 = fmaxf(r1, fmaxf(s[mt][n][2], s[mt][n][3]));
            }
            r0 = fmaxf(r0, __shfl_xor_sync(0xffffffffu, r0, 1));
            r0 = fmaxf(r0, __shfl_xor_sync(0xffffffffu, r0, 2));
            r1 = fmaxf(r1, __shfl_xor_sync(0xffffffffu, r1, 1));
            r1 = fmaxf(r1, __shfl_xor_sync(0xffffffffu, r1, 2));
            const float m0 = fmaxf(mrow[2*mt],   r0);
            const float m1 = fmaxf(mrow[2*mt+1], r1);
            const float c0 = __expf(mrow[2*mt]   - m0);
            const float c1 = __expf(mrow[2*mt+1] - m1);
            mrow[2*mt] = m0; mrow[2*mt+1] = m1;
            float ps0 = 0.f, ps1 = 0.f;
#pragma unroll
            for (int n = 0; n < 8; n++) {
                float e0 = __expf(s[mt][n][0] - m0);
                float e1 = __expf(s[mt][n][1] - m0);
                float e2 = __expf(s[mt][n][2] - m1);
                float e3 = __expf(s[mt][n][3] - m1);
                ps0 += e0 + e1; ps1 += e2 + e3;
                uint32_t t0, t1, t2, t3;
                CVT_TF32(t0, e0); CVT_TF32(t1, e1);
                CVT_TF32(t2, e2); CVT_TF32(t3, e3);
                s[mt][n][0] = uaf(t0); s[mt][n][1] = uaf(t1);
                s[mt][n][2] = uaf(t2); s[mt][n][3] = uaf(t3);
                o[mt][n][0] *= c0; o[mt][n][1] *= c0;
                o[mt][n][2] *= c1; o[mt][n][3] *= c1;
            }
            lrow[2*mt]   = lrow[2*mt]   * c0 + ps0;
            lrow[2*mt+1] = lrow[2*mt+1] * c1 + ps1;
        }

        // ---- O += P @ V (P: c-layout -> a-layout via shuffles) ----
        const int srcA = (lane & ~3) | (l4 >> 1);
        const int srcB = srcA + 2;
#pragma unroll
        for (int kk = 0; kk < 8; kk++) {
            uint32_t pa[2][4];
#pragma unroll
            for (int mt = 0; mt < 2; mt++) {
                float c0 = s[mt][kk][0], c1 = s[mt][kk][1];
                float c2 = s[mt][kk][2], c3 = s[mt][kk][3];
                float x0 = __shfl_sync(0xffffffffu, c0, srcA);
                float x1 = __shfl_sync(0xffffffffu, c1, srcA);
                float y0 = __shfl_sync(0xffffffffu, c0, srcB);
                float y1 = __shfl_sync(0xffffffffu, c1, srcB);
                pa[mt][0] = fau((l4 & 1) ? x1 : x0);
                pa[mt][2] = fau((l4 & 1) ? y1 : y0);
                x0 = __shfl_sync(0xffffffffu, c2, srcA);
                x1 = __shfl_sync(0xffffffffu, c3, srcA);
                y0 = __shfl_sync(0xffffffffu, c2, srcB);
                y1 = __shfl_sync(0xffffffffu, c3, srcB);
                pa[mt][1] = fau((l4 & 1) ? x1 : x0);
                pa[mt][3] = fau((l4 & 1) ? y1 : y0);
            }
#pragma unroll
            for (int n = 0; n < 8; n++) {
                uint32_t vb[2];
                const float* vp = Vs + (kk * 8 + l4) * AST + n * 8 + g;
                vb[0] = fau(vp[0]);
                vb[1] = fau(vp[4 * AST]);
                mma_tf32(o[0][n], pa[0], vb);
                mma_tf32(o[1][n], pa[1], vb);
            }
        }
    }

    // ---- finalize: reduce l across 4-lane group, normalize, write ----
#pragma unroll
    for (int i = 0; i < 4; i++) {
        lrow[i] += __shfl_xor_sync(0xffffffffu, lrow[i], 1);
        lrow[i] += __shfl_xor_sync(0xffffffffu, lrow[i], 2);
        lrow[i] = 1.0f / lrow[i];
    }
#pragma unroll
    for (int mt = 0; mt < 2; mt++) {
        const int rg = b * LL + qbase + warp * 32 + mt * 16 + g;
#pragma unroll
        for (int n = 0; n < 8; n++) {
            const size_t a0 = (size_t)rg * 1024 + h * 64 + n * 8 + 2 * l4;
            *(float2*)(og + a0) =
                make_float2(o[mt][n][0] * lrow[2*mt], o[mt][n][1] * lrow[2*mt]);
            *(float2*)(og + a0 + 8 * 1024) =
                make_float2(o[mt][n][2] * lrow[2*mt+1], o[mt][n][3] * lrow[2*mt+1]);
        }
    }
}

// ---------------------------------------------------------------------------
// Launch
// ---------------------------------------------------------------------------
extern "C" void kernel_launch(void* const* d_in, const int* in_sizes, int n_in,
                              void* d_out, int out_size) {
    const float* x     = (const float*)d_in[0];
    const float* gamma = (const float*)d_in[1];
    const float* beta  = (const float*)d_in[2];
    const float* Wq    = (const float*)d_in[3];
    const float* bq    = (const float*)d_in[4];
    const float* Wk    = (const float*)d_in[5];
    const float* bk    = (const float*)d_in[6];
    const float* Wv    = (const float*)d_in[7];
    const float* bv    = (const float*)d_in[8];
    const float* Wo    = (const float*)d_in[9];
    const float* bo    = (const float*)d_in[10];
    float* out = (float*)d_out;

    float* sc = nullptr;
    cudaGetSymbolAddress((void**)&sc, g_scratch);
    float* xn   = sc;
    float* qb   = sc + 1 * (size_t)ELEMS;
    float* kb   = sc + 2 * (size_t)ELEMS;
    float* vb   = sc + 3 * (size_t)ELEMS;
    float* attn = sc + 4 * (size_t)ELEMS;

    const int attn_smem = (128 + 64 + 64) * AST * sizeof(float);  // 69632
    cudaFuncSetAttribute(attn_tc_kernel,
                         cudaFuncAttributeMaxDynamicSharedMemorySize, attn_smem);

    ln_kernel<<<MM, 256>>>(x, gamma, beta, xn);

    dim3 ggrid(8, 64);
    tgemm_kernel<false><<<ggrid, 256>>>(xn, Wq, bq, nullptr, qb);
    tgemm_kernel<false><<<ggrid, 256>>>(xn, Wk, bk, nullptr, kb);
    tgemm_kernel<false><<<ggrid, 256>>>(xn, Wv, bv, nullptr, vb);

    rope_kernel<<<(BB * LL * NH * 32) / 256, 256>>>(qb, kb);

    dim3 agrid(LL / 128, BB * NH);
    attn_tc_kernel<<<agrid, 128, attn_smem>>>(qb, kb, vb, attn);

    tgemm_kernel<true><<<ggrid, 256>>>(attn, Wo, bo, x, out);
}

// round 6
// speedup vs baseline: 1.1636x; 1.1636x over previous
#include <cuda_runtime.h>
#include <math.h>
#include <stdint.h>

// Problem constants
#define BB 4
#define LL 2048
#define DM 1024
#define NH 16
#define DH 64
#define MM (BB*LL)          // 8192 rows
#define ELEMS (MM*DM)       // 8388608 floats per tensor
#define WELEMS (DM*DM)      // 1048576

// Scratch: xn,q,k,v,attn (5x) + 4 tf32 weights + rope table (131072 floats)
__device__ float g_scratch[5 * (size_t)ELEMS + 4 * (size_t)WELEMS + 131072];

#define CVT_TF32(u, f) asm("cvt.rna.tf32.f32 %0, %1;" : "=r"(u) : "f"(f))
__device__ __forceinline__ uint32_t fau(float f) { return __float_as_uint(f); }
__device__ __forceinline__ float uaf(uint32_t u) { return __uint_as_float(u); }

__device__ __forceinline__ void mma_tf32(float c[4],
                                         const uint32_t a[4],
                                         const uint32_t b[2]) {
    asm volatile(
        "mma.sync.aligned.m16n8k8.row.col.f32.tf32.tf32.f32 "
        "{%0,%1,%2,%3}, {%4,%5,%6,%7}, {%8,%9}, {%0,%1,%2,%3};\n"
        : "+f"(c[0]), "+f"(c[1]), "+f"(c[2]), "+f"(c[3])
        : "r"(a[0]), "r"(a[1]), "r"(a[2]), "r"(a[3]),
          "r"(b[0]), "r"(b[1]));
}

#define CP_ASYNC16(dst, src) \
    asm volatile("cp.async.cg.shared.global [%0], [%1], 16;\n" \
                 :: "r"(dst), "l"(src) : "memory")
#define CP_COMMIT() asm volatile("cp.async.commit_group;\n" ::: "memory")
#define CP_WAIT1()  asm volatile("cp.async.wait_group 1;\n" ::: "memory")

// ---------------------------------------------------------------------------
// Elementwise fp32 -> tf32 rounding (for weight matrices), float4
// ---------------------------------------------------------------------------
__global__ __launch_bounds__(256) void cvtw_kernel(const float* __restrict__ src,
                                                   float* __restrict__ dst) {
    const int i = blockIdx.x * 256 + threadIdx.x;
    float4 v = ((const float4*)src)[i];
    uint32_t u0, u1, u2, u3;
    CVT_TF32(u0, v.x); CVT_TF32(u1, v.y);
    CVT_TF32(u2, v.z); CVT_TF32(u3, v.w);
    ((float4*)dst)[i] = make_float4(uaf(u0), uaf(u1), uaf(u2), uaf(u3));
}

// ---------------------------------------------------------------------------
// RoPE cos/sin table: t[l*32+p] = {cos(l*invfreq(p)), sin(...)}
// ---------------------------------------------------------------------------
__global__ __launch_bounds__(256) void rope_table_kernel(float2* __restrict__ t) {
    const int idx = blockIdx.x * 256 + threadIdx.x;   // 65536
    const int l = idx >> 5, p = idx & 31;
    const float inv = exp2f((float)p * (-2.0f / 64.0f) * 13.2877123795494f);
    float s, c;
    sincosf((float)l * inv, &s, &c);
    t[idx] = make_float2(c, s);
}

// ---------------------------------------------------------------------------
// LayerNorm -> tf32-rounded output
// ---------------------------------------------------------------------------
__global__ __launch_bounds__(256) void ln_kernel(const float* __restrict__ x,
                                                 const float* __restrict__ gamma,
                                                 const float* __restrict__ beta,
                                                 float* __restrict__ xn) {
    const int row = blockIdx.x;
    const int t = threadIdx.x;
    const float4 v = ((const float4*)(x + (size_t)row * DM))[t];
    __shared__ float red[8];

    float s = v.x + v.y + v.z + v.w;
#pragma unroll
    for (int o = 16; o > 0; o >>= 1) s += __shfl_xor_sync(0xffffffffu, s, o);
    if ((t & 31) == 0) red[t >> 5] = s;
    __syncthreads();
    float mean = (red[0]+red[1]+red[2]+red[3]+red[4]+red[5]+red[6]+red[7]) * (1.0f/DM);

    float dx = v.x-mean, dy = v.y-mean, dz = v.z-mean, dw = v.w-mean;
    float q = dx*dx + dy*dy + dz*dz + dw*dw;
#pragma unroll
    for (int o = 16; o > 0; o >>= 1) q += __shfl_xor_sync(0xffffffffu, q, o);
    __syncthreads();
    if ((t & 31) == 0) red[t >> 5] = q;
    __syncthreads();
    float var = (red[0]+red[1]+red[2]+red[3]+red[4]+red[5]+red[6]+red[7]) * (1.0f/DM);
    float rs = rsqrtf(var + 1e-5f);

    const float4 g4 = ((const float4*)gamma)[t];
    const float4 b4 = ((const float4*)beta)[t];
    uint32_t u0, u1, u2, u3;
    CVT_TF32(u0, dx*rs*g4.x + b4.x);
    CVT_TF32(u1, dy*rs*g4.y + b4.y);
    CVT_TF32(u2, dz*rs*g4.z + b4.z);
    CVT_TF32(u3, dw*rs*g4.w + b4.w);
    ((float4*)(xn + (size_t)row * DM))[t] =
        make_float4(uaf(u0), uaf(u1), uaf(u2), uaf(u3));
}

// ---------------------------------------------------------------------------
// TF32 GEMM, cp.async 3-stage: C[M,1024] = A@W + bias (+resid) (+rope)
// A, W already tf32-rounded. 128x128x16 tile, 8 warps (2Mx4N), 64x32 warp.
// Smem: As[3][128][20], Bs[3][16][136]
// ---------------------------------------------------------------------------
#define AS_STG 2560          // 128*20
#define BS_STG 2176          // 16*136
#define BS_BASE (3*AS_STG)   // 7680
#define GSMEM ((3*AS_STG + 3*BS_STG) * 4)  // 56832 bytes

template <bool RESID, bool ROPE>
__global__ __launch_bounds__(256) void tgemm2(const float* __restrict__ A,
                                              const float* __restrict__ W,
                                              const float* __restrict__ bias,
                                              const float* __restrict__ resid,
                                              const float2* __restrict__ rtab,
                                              float* __restrict__ C) {
    constexpr int NK = 64;   // 1024/16
    extern __shared__ float sm2[];

    const int tid   = threadIdx.x;
    const int lane  = tid & 31;
    const int warp  = tid >> 5;
    const int warpM = warp >> 2;
    const int warpN = warp & 3;
    const int g  = lane >> 2;
    const int l4 = lane & 3;
    const int brow = blockIdx.y;
    const int bcol = blockIdx.x;

    const float* Ab = A + (size_t)brow * 128 * 1024;
    const float* Wb = W + bcol * 128;

    const uint32_t smbase = (uint32_t)__cvta_generic_to_shared(sm2);

    // async-copy assignments: 512 16B chunks each for A and B per stage
    const int arow0 = tid >> 2, akc = (tid & 3) << 2;       // A chunk 0
    const int brow0 = tid >> 5, bnc = (tid & 31) << 2;      // B chunk 0

    auto issue = [&](int stage, int k0) {
#pragma unroll
        for (int it = 0; it < 2; it++) {
            const int row = arow0 + it * 64;
            const uint32_t dst = smbase + (stage * AS_STG + row * 20 + akc) * 4;
            CP_ASYNC16(dst, Ab + (size_t)row * 1024 + k0 + akc);
        }
#pragma unroll
        for (int it = 0; it < 2; it++) {
            const int row = brow0 + it * 8;
            const uint32_t dst = smbase + (BS_BASE + stage * BS_STG + row * 136 + bnc) * 4;
            CP_ASYNC16(dst, Wb + (size_t)(k0 + row) * 1024 + bnc);
        }
    };

    float acc[16][4];
#pragma unroll
    for (int i = 0; i < 16; i++)
#pragma unroll
        for (int j = 0; j < 4; j++) acc[i][j] = 0.f;

    auto compute = [&](int stage) {
        const float* Ast = sm2 + stage * AS_STG;
        const float* Bst = sm2 + BS_BASE + stage * BS_STG;
#pragma unroll
        for (int k8 = 0; k8 < 16; k8 += 8) {
            uint32_t af[4][4];
            uint32_t bf[4][2];
#pragma unroll
            for (int i = 0; i < 4; i++) {
                const float* p = Ast + (warpM * 64 + i * 16 + g) * 20 + k8 + l4;
                af[i][0] = fau(p[0]);
                af[i][1] = fau(p[8 * 20]);
                af[i][2] = fau(p[4]);
                af[i][3] = fau(p[8 * 20 + 4]);
            }
#pragma unroll
            for (int j = 0; j < 4; j++) {
                const float* p = Bst + (k8 + l4) * 136 + warpN * 32 + j * 8 + g;
                bf[j][0] = fau(p[0]);
                bf[j][1] = fau(p[4 * 136]);
            }
#pragma unroll
            for (int i = 0; i < 4; i++)
#pragma unroll
                for (int j = 0; j < 4; j++)
                    mma_tf32(acc[i * 4 + j], af[i], bf[j]);
        }
    };

    // prologue
    issue(0, 0);  CP_COMMIT();
    issue(1, 16); CP_COMMIT();

    for (int kt = 0; kt < NK; kt++) {
        CP_WAIT1();
        __syncthreads();
        if (kt + 2 < NK) issue((kt + 2) % 3, (kt + 2) * 16);
        CP_COMMIT();
        compute(kt % 3);
    }

    // ---- epilogue ----
#pragma unroll
    for (int i = 0; i < 4; i++) {
        const int r0 = brow * 128 + warpM * 64 + i * 16 + g;
#pragma unroll
        for (int j = 0; j < 4; j++) {
            const int cc = bcol * 128 + warpN * 32 + j * 8 + (l4 << 1);
            const float bx = bias[cc], by = bias[cc + 1];
            float v0x = acc[i * 4 + j][0] + bx;
            float v0y = acc[i * 4 + j][1] + by;
            float v1x = acc[i * 4 + j][2] + bx;
            float v1y = acc[i * 4 + j][3] + by;
            if (ROPE) {
                const int p  = (cc & 63) >> 1;
                const int l0 = r0 & (LL - 1);
                const float2 cs0 = rtab[l0 * 32 + p];
                const float2 cs1 = rtab[(l0 + 8) * 32 + p];
                float t;
                t   = v0x * cs0.x - v0y * cs0.y;
                v0y = v0x * cs0.y + v0y * cs0.x;
                v0x = t;
                t   = v1x * cs1.x - v1y * cs1.y;
                v1y = v1x * cs1.y + v1y * cs1.x;
                v1x = t;
            }
            if (RESID) {
                const float2 r0v = *(const float2*)(resid + (size_t)r0 * 1024 + cc);
                const float2 r1v = *(const float2*)(resid + (size_t)(r0 + 8) * 1024 + cc);
                v0x += r0v.x; v0y += r0v.y;
                v1x += r1v.x; v1y += r1v.y;
            }
            *(float2*)(C + (size_t)r0 * 1024 + cc)       = make_float2(v0x, v0y);
            *(float2*)(C + (size_t)(r0 + 8) * 1024 + cc) = make_float2(v1x, v1y);
        }
    }
}

// ---------------------------------------------------------------------------
// Tensor-core flash attention (causal, TF32 mma), tf32-rounded output
// ---------------------------------------------------------------------------
#define AST 68

__global__ __launch_bounds__(128) void attn_tc_kernel(const float* __restrict__ qg,
                                                      const float* __restrict__ kg,
                                                      const float* __restrict__ vg,
                                                      float* __restrict__ og) {
    extern __shared__ float sm[];
    float* Qs = sm;
    float* Ks = sm + 128 * AST;
    float* Vs = Ks + 64 * AST;

    const int bh = blockIdx.y;
    const int b = bh >> 4, h = bh & 15;
    const int qt = (int)gridDim.x - 1 - (int)blockIdx.x;
    const int qbase = qt * 128;
    const int tid  = threadIdx.x;
    const int lane = tid & 31;
    const int warp = tid >> 5;
    const int g  = lane >> 2;
    const int l4 = lane & 3;

    const float4* qgp = (const float4*)qg;
    for (int i = tid; i < 128 * 16; i += 128) {
        const int row = i >> 4, q4 = i & 15;
        float4 v = qgp[(size_t)(b * LL + qbase + row) * 256 + h * 16 + q4];
        uint32_t u0, u1, u2, u3;
        CVT_TF32(u0, v.x * 0.125f);
        CVT_TF32(u1, v.y * 0.125f);
        CVT_TF32(u2, v.z * 0.125f);
        CVT_TF32(u3, v.w * 0.125f);
        float* dst = Qs + row * AST + q4 * 4;
        dst[0] = uaf(u0); dst[1] = uaf(u1); dst[2] = uaf(u2); dst[3] = uaf(u3);
    }

    float s[2][8][4];
    float o[2][8][4];
#pragma unroll
    for (int mt = 0; mt < 2; mt++)
#pragma unroll
        for (int n = 0; n < 8; n++)
#pragma unroll
            for (int i = 0; i < 4; i++) o[mt][n][i] = 0.f;
    float mrow[4] = {-1e30f, -1e30f, -1e30f, -1e30f};
    float lrow[4] = {0.f, 0.f, 0.f, 0.f};

    const int ntiles = 2 * qt + 2;
    for (int t64 = 0; t64 < ntiles; t64++) {
        const int j0 = t64 * 64;
        __syncthreads();
        for (int i = tid; i < 64 * 16; i += 128) {
            const int row = i >> 4, q4 = i & 15;
            const size_t gi = (size_t)(b * LL + j0 + row) * 256 + h * 16 + q4;
            float4 kv = ((const float4*)kg)[gi];
            float4 vv = ((const float4*)vg)[gi];
            uint32_t u0, u1, u2, u3;
            CVT_TF32(u0, kv.x); CVT_TF32(u1, kv.y);
            CVT_TF32(u2, kv.z); CVT_TF32(u3, kv.w);
            float* kd = Ks + row * AST + q4 * 4;
            kd[0] = uaf(u0); kd[1] = uaf(u1); kd[2] = uaf(u2); kd[3] = uaf(u3);
            CVT_TF32(u0, vv.x); CVT_TF32(u1, vv.y);
            CVT_TF32(u2, vv.z); CVT_TF32(u3, vv.w);
            float* vd = Vs + row * AST + q4 * 4;
            vd[0] = uaf(u0); vd[1] = uaf(u1); vd[2] = uaf(u2); vd[3] = uaf(u3);
        }
        __syncthreads();

#pragma unroll
        for (int mt = 0; mt < 2; mt++)
#pragma unroll
            for (int n = 0; n < 8; n++)
#pragma unroll
                for (int i = 0; i < 4; i++) s[mt][n][i] = 0.f;

#pragma unroll
        for (int kk = 0; kk < 8; kk++) {
            uint32_t qa[2][4];
#pragma unroll
            for (int mt = 0; mt < 2; mt++) {
                const float* qp = Qs + (warp * 32 + mt * 16 + g) * AST + kk * 8 + l4;
                qa[mt][0] = fau(qp[0]);
                qa[mt][2] = fau(qp[4]);
                qa[mt][1] = fau(qp[8 * AST]);
                qa[mt][3] = fau(qp[8 * AST + 4]);
            }
#pragma unroll
            for (int n = 0; n < 8; n++) {
                uint32_t kb[2];
                const float* kp = Ks + (n * 8 + g) * AST + kk * 8 + l4;
                kb[0] = fau(kp[0]);
                kb[1] = fau(kp[4]);
                mma_tf32(s[0][n], qa[0], kb);
                mma_tf32(s[1][n], qa[1], kb);
            }
        }

        if (t64 >= 2 * qt) {
#pragma unroll
            for (int mt = 0; mt < 2; mt++) {
                const int rg = qbase + warp * 32 + mt * 16 + g;
#pragma unroll
                for (int n = 0; n < 8; n++) {
                    const int c0 = j0 + n * 8 + 2 * l4;
                    if (c0     > rg)     s[mt][n][0] = -1e30f;
                    if (c0 + 1 > rg)     s[mt][n][1] = -1e30f;
                    if (c0     > rg + 8) s[mt][n][2] = -1e30f;
                    if (c0 + 1 > rg + 8) s[mt][n][3] = -1e30f;
                }
            }
        }

#pragma unroll
        for (int mt = 0; mt < 2; mt++) {
            float r0 = -1e30f, r1 = -1e30f;
#pragma unroll
            for (int n = 0; n < 8; n++) {
                r0 = fmaxf(r0, fmaxf(s[mt][n][0], s[mt][n][1]));
                r1 = fmaxf(r1, fmaxf(s[mt][n][2], s[mt][n][3]));
            }
            r0 = fmaxf(r0, __shfl_xor_sync(0xffffffffu, r0, 1));
            r0 = fmaxf(r0, __shfl_xor_sync(0xffffffffu, r0, 2));
            r1 = fmaxf(r1, __shfl_xor_sync(0xffffffffu, r1, 1));
            r1 = fmaxf(r1, __shfl_xor_sync(0xffffffffu, r1, 2));
            const float m0 = fmaxf(mrow[2*mt],   r0);
            const float m1 = fmaxf(mrow[2*mt+1], r1);
            const float c0 = __expf(mrow[2*mt]   - m0);
            const float c1 = __expf(mrow[2*mt+1] - m1);
            mrow[2*mt] = m0; mrow[2*mt+1] = m1;
            float ps0 = 0.f, ps1 = 0.f;
#pragma unroll
            for (int n = 0; n < 8; n++) {
                float e0 = __expf(s[mt][n][0] - m0);
                float e1 = __expf(s[mt][n][1] - m0);
                float e2 = __expf(s[mt][n][2] - m1);
                float e3 = __expf(s[mt][n][3] - m1);
                ps0 += e0 + e1; ps1 += e2 + e3;
                uint32_t t0, t1, t2, t3;
                CVT_TF32(t0, e0); CVT_TF32(t1, e1);
                CVT_TF32(t2, e2); CVT_TF32(t3, e3);
                s[mt][n][0] = uaf(t0); s[mt][n][1] = uaf(t1);
                s[mt][n][2] = uaf(t2); s[mt][n][3] = uaf(t3);
                o[mt][n][0] *= c0; o[mt][n][1] *= c0;
                o[mt][n][2] *= c1; o[mt][n][3] *= c1;
            }
            lrow[2*mt]   = lrow[2*mt]   * c0 + ps0;
            lrow[2*mt+1] = lrow[2*mt+1] * c1 + ps1;
        }

        const int srcA = (lane & ~3) | (l4 >> 1);
        const int srcB = srcA + 2;
#pragma unroll
        for (int kk = 0; kk < 8; kk++) {
            uint32_t pa[2][4];
#pragma unroll
            for (int mt = 0; mt < 2; mt++) {
                float c0 = s[mt][kk][0], c1 = s[mt][kk][1];
                float c2 = s[mt][kk][2], c3 = s[mt][kk][3];
                float x0 = __shfl_sync(0xffffffffu, c0, srcA);
                float x1 = __shfl_sync(0xffffffffu, c1, srcA);
                float y0 = __shfl_sync(0xffffffffu, c0, srcB);
                float y1 = __shfl_sync(0xffffffffu, c1, srcB);
                pa[mt][0] = fau((l4 & 1) ? x1 : x0);
                pa[mt][2] = fau((l4 & 1) ? y1 : y0);
                x0 = __shfl_sync(0xffffffffu, c2, srcA);
                x1 = __shfl_sync(0xffffffffu, c3, srcA);
                y0 = __shfl_sync(0xffffffffu, c2, srcB);
                y1 = __shfl_sync(0xffffffffu, c3, srcB);
                pa[mt][1] = fau((l4 & 1) ? x1 : x0);
                pa[mt][3] = fau((l4 & 1) ? y1 : y0);
            }
#pragma unroll
            for (int n = 0; n < 8; n++) {
                uint32_t vb[2];
                const float* vp = Vs + (kk * 8 + l4) * AST + n * 8 + g;
                vb[0] = fau(vp[0]);
                vb[1] = fau(vp[4 * AST]);
                mma_tf32(o[0][n], pa[0], vb);
                mma_tf32(o[1][n], pa[1], vb);
            }
        }
    }

#pragma unroll
    for (int i = 0; i < 4; i++) {
        lrow[i] += __shfl_xor_sync(0xffffffffu, lrow[i], 1);
        lrow[i] += __shfl_xor_sync(0xffffffffu, lrow[i], 2);
        lrow[i] = 1.0f / lrow[i];
    }
#pragma unroll
    for (int mt = 0; mt < 2; mt++) {
        const int rg = b * LL + qbase + warp * 32 + mt * 16 + g;
#pragma unroll
        for (int n = 0; n < 8; n++) {
            const size_t a0 = (size_t)rg * 1024 + h * 64 + n * 8 + 2 * l4;
            uint32_t u0, u1, u2, u3;
            CVT_TF32(u0, o[mt][n][0] * lrow[2*mt]);
            CVT_TF32(u1, o[mt][n][1] * lrow[2*mt]);
            CVT_TF32(u2, o[mt][n][2] * lrow[2*mt+1]);
            CVT_TF32(u3, o[mt][n][3] * lrow[2*mt+1]);
            *(float2*)(og + a0)            = make_float2(uaf(u0), uaf(u1));
            *(float2*)(og + a0 + 8 * 1024) = make_float2(uaf(u2), uaf(u3));
        }
    }
}

// ---------------------------------------------------------------------------
// Launch
// ---------------------------------------------------------------------------
extern "C" void kernel_launch(void* const* d_in, const int* in_sizes, int n_in,
                              void* d_out, int out_size) {
    const float* x     = (const float*)d_in[0];
    const float* gamma = (const float*)d_in[1];
    const float* beta  = (const float*)d_in[2];
    const float* Wq    = (const float*)d_in[3];
    const float* bq    = (const float*)d_in[4];
    const float* Wk    = (const float*)d_in[5];
    const float* bk    = (const float*)d_in[6];
    const float* Wv    = (const float*)d_in[7];
    const float* bv    = (const float*)d_in[8];
    const float* Wo    = (const float*)d_in[9];
    const float* bo    = (const float*)d_in[10];
    float* out = (float*)d_out;

    float* sc = nullptr;
    cudaGetSymbolAddress((void**)&sc, g_scratch);
    float* xn   = sc;
    float* qb   = sc + 1 * (size_t)ELEMS;
    float* kb   = sc + 2 * (size_t)ELEMS;
    float* vb   = sc + 3 * (size_t)ELEMS;
    float* attn = sc + 4 * (size_t)ELEMS;
    float* Wqt  = sc + 5 * (size_t)ELEMS;
    float* Wkt  = Wqt + (size_t)WELEMS;
    float* Wvt  = Wkt + (size_t)WELEMS;
    float* Wot  = Wvt + (size_t)WELEMS;
    float2* rtab = (float2*)(Wot + (size_t)WELEMS);

    const int attn_smem = (128 + 64 + 64) * AST * sizeof(float);
    cudaFuncSetAttribute(attn_tc_kernel,
                         cudaFuncAttributeMaxDynamicSharedMemorySize, attn_smem);
    cudaFuncSetAttribute(tgemm2<false, true>,
                         cudaFuncAttributeMaxDynamicSharedMemorySize, GSMEM);
    cudaFuncSetAttribute(tgemm2<false, false>,
                         cudaFuncAttributeMaxDynamicSharedMemorySize, GSMEM);
    cudaFuncSetAttribute(tgemm2<true, false>,
                         cudaFuncAttributeMaxDynamicSharedMemorySize, GSMEM);

    rope_table_kernel<<<65536 / 256, 256>>>(rtab);
    cvtw_kernel<<<WELEMS / 1024, 256>>>(Wq, Wqt);
    cvtw_kernel<<<WELEMS / 1024, 256>>>(Wk, Wkt);
    cvtw_kernel<<<WELEMS / 1024, 256>>>(Wv, Wvt);
    cvtw_kernel<<<WELEMS / 1024, 256>>>(Wo, Wot);

    ln_kernel<<<MM, 256>>>(x, gamma, beta, xn);

    dim3 ggrid(8, 64);
    tgemm2<false, true ><<<ggrid, 256, GSMEM>>>(xn, Wqt, bq, nullptr, rtab, qb);
    tgemm2<false, true ><<<ggrid, 256, GSMEM>>>(xn, Wkt, bk, nullptr, rtab, kb);
    tgemm2<false, false><<<ggrid, 256, GSMEM>>>(xn, Wvt, bv, nullptr, rtab, vb);

    dim3 agrid(LL / 128, BB * NH);
    attn_tc_kernel<<<agrid, 128, attn_smem>>>(qb, kb, vb, attn);

    tgemm2<true, false><<<ggrid, 256, GSMEM>>>(attn, Wot, bo, x, rtab, out);
}